// round 5
// baseline (speedup 1.0000x reference)
#include <cuda_runtime.h>

#define FULL_MASK 0xffffffffu
typedef unsigned long long ull;

// ---- f32x2 packed-math helpers ----
__device__ __forceinline__ ull pk2(float lo, float hi) {
    ull r; asm("mov.b64 %0,{%1,%2};" : "=l"(r) : "f"(lo), "f"(hi)); return r;
}
__device__ __forceinline__ void up2(ull v, float& lo, float& hi) {
    asm("mov.b64 {%0,%1},%2;" : "=f"(lo), "=f"(hi) : "l"(v));
}
__device__ __forceinline__ ull fma2(ull a, ull b, ull c) {
    ull d; asm("fma.rn.f32x2 %0,%1,%2,%3;" : "=l"(d) : "l"(a), "l"(b), "l"(c)); return d;
}
__device__ __forceinline__ ull mul2(ull a, ull b) {
    ull d; asm("mul.rn.f32x2 %0,%1,%2;" : "=l"(d) : "l"(a), "l"(b)); return d;
}
__device__ __forceinline__ ull add2(ull a, ull b) {
    ull d; asm("add.rn.f32x2 %0,%1,%2;" : "=l"(d) : "l"(a), "l"(b)); return d;
}
__device__ __forceinline__ float tanh_hw(float x) {
    float y; asm("tanh.approx.f32 %0, %1;" : "=f"(y) : "f"(x)); return y;
}

// Forward-Euler ScaledODENet, one warp per batch element.
//
// Carried state U = b1 + W1s^T ys (64-vec, packed 2/lane).
//   a   = U + x_t*w0 ; h = tanh(a)
//   per-lane W2 partials in XOR-permuted slots: slot i <-> output i^(l&15)
//   radix-16 reduce-scatter (ONE shuffle round): lane l gets the half-warp
//     sum for output l&15
//   fold+allgather merged (ONE shuffle round): d[j] = shfl(dh,j)+shfl(dh,j+16)
//   U  += sum_j d_j * W1col_j + c
//   ys0 += d_0 + b2[0]/sr  (lane 0 writes out; off the critical chain)
__global__ __launch_bounds__(32, 1)
void ode_fe_kernel(const float* __restrict__ x,
                   const float* __restrict__ W1,
                   const float* __restrict__ b1,
                   const float* __restrict__ b2,
                   const float* __restrict__ W2,
                   float* __restrict__ out,
                   int T) {
    constexpr int B = 32;
    const int b = blockIdx.x;
    const int l = threadIdx.x;              // owns hidden units l, l+32
    const float inv_sr = 1.0f / 44100.0f;
    const int perm = l & 15;

    // ---- one-time weight staging ----
    const ull w02 = pk2(W1[l], W1[l + 32]);          // W1 row 0 (x weights)

    // W2 rows l, l+32 pre-scaled by 1/sr, slot i holds output (i ^ perm);
    // packed over adjacent slots (2m, 2m+1).
    ull w2A[8], w2B[8];
#pragma unroll
    for (int m = 0; m < 8; ++m) {
        const int j0 = (2 * m) ^ perm, j1 = (2 * m + 1) ^ perm;
        w2A[m] = pk2(W2[l * 16 + j0] * inv_sr,        W2[l * 16 + j1] * inv_sr);
        w2B[m] = pk2(W2[(l + 32) * 16 + j0] * inv_sr, W2[(l + 32) * 16 + j1] * inv_sr);
    }

    // W1 state columns packed per j: (row feeding unit l, unit l+32)
    ull w1c2[16];
#pragma unroll
    for (int j = 0; j < 16; ++j)
        w1c2[j] = pk2(W1[(j + 1) * 64 + l], W1[(j + 1) * 64 + l + 32]);

    // c = W1s^T (b2/sr), per-step constant, seeds the U fma tree
    float clo = 0.0f, chi = 0.0f;
#pragma unroll
    for (int j = 0; j < 16; ++j) {
        const float bj = b2[j] * inv_sr;
        clo = fmaf(bj, W1[(j + 1) * 64 + l],      clo);
        chi = fmaf(bj, W1[(j + 1) * 64 + l + 32], chi);
    }
    const ull c2 = pk2(clo, chi);
    const float b20s = b2[0] * inv_sr;

    // ---- loop-carried state ----
    ull U2 = pk2(b1[l], b1[l + 32]);        // U = b1 + W1s^T ys (ys starts 0)
    float ys0 = 0.0f;

    if (l == 0) out[b] = 0.0f;              // t=0 output row is zeros
    const int nsteps = T - 1;

    // x prefetch: 32 timesteps per register, one block ahead
    float xbuf  = (l < nsteps)      ? x[l * B + b]        : 0.0f;
    float xnext = (l + 32 < nsteps) ? x[(l + 32) * B + b] : 0.0f;
    float xt = __shfl_sync(FULL_MASK, xbuf, 0);

#pragma unroll 1
    for (int t = 0; t < nsteps; ++t) {
        // ---- a = U + x*w0 ; h = tanh(a) ----
        const ull a2 = fma2(pk2(xt, xt), w02, U2);
        float alo, ahi;
        up2(a2, alo, ahi);
        const float hlo = tanh_hw(alo);
        const float hhi = tanh_hw(ahi);

        // ---- packed per-lane W2 partials, scalar slot views ----
        const ull h2lo = pk2(hlo, hlo);
        const ull h2hi = pk2(hhi, hhi);
        float v[16];
#pragma unroll
        for (int m = 0; m < 8; ++m) {
            const ull p2 = fma2(h2lo, w2A[m], mul2(h2hi, w2B[m]));
            up2(p2, v[2 * m], v[2 * m + 1]);
        }

        // ---- radix-16 reduce-scatter: ONE dependent shuffle round ----
        // lane l accumulates the half-warp sum of output (l & 15)
        float g[15];
#pragma unroll
        for (int o = 1; o < 16; ++o)
            g[o - 1] = __shfl_xor_sync(FULL_MASK, v[o], o);
        const float t0 = (g[0] + g[1])   + (g[2] + g[3]);
        const float t1 = (g[4] + g[5])   + (g[6] + g[7]);
        const float t2 = (g[8] + g[9])   + (g[10] + g[11]);
        const float t3 = (g[12] + g[13]) + (g[14] + v[0]);
        const float dh = (t0 + t1) + (t2 + t3);

        // ---- fold + allgather merged: ONE more shuffle round ----
        float d[16];
#pragma unroll
        for (int j = 0; j < 16; ++j)
            d[j] = __shfl_sync(FULL_MASK, dh, j) +
                   __shfl_sync(FULL_MASK, dh, j + 16);

        // ---- output channel (off the critical chain) ----
        ys0 += d[0] + b20s;
        if (l == 0) out[(t + 1) * B + b] = ys0;

        // refill / prefetch next xt (independent of U update)
        if ((t & 31) == 31) {
            xbuf = xnext;
            const int tn = t + 33 + l;
            xnext = (tn < nsteps) ? x[tn * B + b] : 0.0f;
        }
        xt = __shfl_sync(FULL_MASK, xbuf, (t + 1) & 31);

        // ---- U += sum_j d_j * W1col_j + c  (packed, 4-wide trees) ----
        ull s0 = fma2(pk2(d[0], d[0]),   w1c2[0],  c2);
        ull s1 = mul2(pk2(d[4], d[4]),   w1c2[4]);
        ull s2 = mul2(pk2(d[8], d[8]),   w1c2[8]);
        ull s3 = mul2(pk2(d[12], d[12]), w1c2[12]);
#pragma unroll
        for (int j = 1; j < 4; ++j) {
            s0 = fma2(pk2(d[j],      d[j]),      w1c2[j],      s0);
            s1 = fma2(pk2(d[j + 4],  d[j + 4]),  w1c2[j + 4],  s1);
            s2 = fma2(pk2(d[j + 8],  d[j + 8]),  w1c2[j + 8],  s2);
            s3 = fma2(pk2(d[j + 12], d[j + 12]), w1c2[j + 12], s3);
        }
        U2 = add2(U2, add2(add2(s0, s1), add2(s2, s3)));
    }
}

extern "C" void kernel_launch(void* const* d_in, const int* in_sizes, int n_in,
                              void* d_out, int out_size) {
    const float* x  = (const float*)d_in[0];
    const float* W1 = (const float*)d_in[1];
    const float* b1 = (const float*)d_in[2];
    const float* W2 = (const float*)d_in[3];
    const float* b2 = (const float*)d_in[4];
    float* out = (float*)d_out;

    const int T = in_sizes[0] / 32;   // x is (T, B=32, F=1)
    ode_fe_kernel<<<32, 32>>>(x, W1, b1, b2, W2, out, T);
}